// round 2
// baseline (speedup 1.0000x reference)
#include <cuda_runtime.h>

namespace {

constexpr int H = 4096, W = 4096;
constexpr int TW = 128;        // output cols per block
constexpr int TH = 32;         // output rows per block
constexpr int LW = TW + 4;     // loaded cols: c0-2 .. c0+TW+1
constexpr int SPITCH = 133;    // odd pitch -> conflict-free row-strided LDS
constexpr int OPITCH = 129;    // odd pitch for output staging
constexpr int NT = 256;
constexpr int RUN = 16;        // output cols per thread

__global__ void __launch_bounds__(NT) sobel_canny(const float* __restrict__ x,
                                                  float* __restrict__ out) {
    __shared__ float s[(TH + 2) * SPITCH];   // input tile + halo
    __shared__ float so[TH * OPITCH];        // output staging

    const int c0 = blockIdx.x * TW;
    const int r0 = blockIdx.y * TH;
    const int tid = threadIdx.x;

    // ---- load input tile with halo: rows r0-1..r0+TH, cols c0-2..c0+TW+1 ----
    for (int i = tid; i < (TH + 2) * LW; i += NT) {
        int r = i / LW;
        int c = i - r * LW;
        int gr = r0 - 1 + r;
        int gc = c0 - 2 + c;
        float v = 0.0f;
        if ((unsigned)gr < (unsigned)H && (unsigned)gc < (unsigned)W)
            v = __ldg(x + gr * W + gc);
        s[r * SPITCH + c] = v;
    }
    __syncthreads();

    // ---- compute: warp spans 32 rows (conflict-free smem), 16 cols/thread ----
    const int row = tid & 31;      // local output row
    const int cg  = tid >> 5;      // column group 0..7
    const int lc0 = cg * RUN;      // local output col base
    const float* st = s + row * SPITCH;   // input row gr-1
    const float* sm = st + SPITCH;        // input row gr
    const float* sb = sm + SPITCH;        // input row gr+1

    // A(j) = t + 2m + b (column sum for gx), B(j) = t - b (for gy)
    // at smem column sc = lc0 + 2 + j
    auto ab = [&](int j, float& A, float& B) {
        int sc = lc0 + 2 + j;
        float t = st[sc], m = sm[sc], b = sb[sc];
        A = __fadd_rn(__fadd_rn(t, __fmul_rn(2.0f, m)), b);
        B = __fsub_rn(t, b);
    };
    // mag(j): gx = A(j+1)-A(j-1), gy = B(j-1)+2B(j)+B(j+1)
    auto magf = [](float Am, float Ap, float Bm, float Bc, float Bp) {
        float gx = __fsub_rn(Ap, Am);
        float gy = __fadd_rn(__fadd_rn(Bm, __fmul_rn(2.0f, Bc)), Bp);
        return __fsqrt_rn(__fadd_rn(__fmul_rn(gx, gx), __fmul_rn(gy, gy)));
    };

    float A0, B0, A1, B1, A2, B2, A3, B3;
    ab(-2, A0, B0);
    ab(-1, A1, B1);
    ab(0,  A2, B2);
    ab(1,  A3, B3);
    float magm = magf(A0, A2, B0, B1, B2);   // mag at j = -1
    float magc = magf(A1, A3, B1, B2, B3);   // mag at j =  0
    // rolling state for iteration j: Aa=A(j), Ab_=A(j+1), same for B
    float Aa = A2, Ab_ = A3, Ba = B2, Bb = B3;

    const int gr = r0 + row;
    const bool rEdge = (gr == 0) || (gr == H - 1);
    float* orow = so + row * OPITCH;

#pragma unroll
    for (int j = 0; j < RUN; j++) {
        float An, Bn;
        ab(j + 2, An, Bn);
        float magn = magf(Aa, An, Ba, Bb, Bn);   // mag at j+1

        // NMS: direction branch b1 is always true (radians vs degree thresholds),
        // so comparison is strictly horizontal.
        float mc = magc;
        float e = ((mc >= magm) && (mc >= magn)) ? mc : 0.0f;
        // double threshold: strong -> 255, weak [0.05, 0.15] -> 0, else pass e
        float o = (e > 0.15f) ? 255.0f : ((e >= 0.05f) ? 0.0f : e);
        int gc = c0 + lc0 + j;
        if (rEdge || gc == 0 || gc == W - 1) o = 0.0f;   // border rows/cols
        orow[lc0 + j] = o;

        Aa = Ab_; Ab_ = An;
        Ba = Bb;  Bb  = Bn;
        magm = magc; magc = magn;
    }
    __syncthreads();

    // ---- coalesced writeback: consecutive lanes -> consecutive columns ----
    for (int k = tid; k < TH * TW; k += NT) {
        int r = k >> 7;        // / TW
        int c = k & (TW - 1);
        out[(r0 + r) * W + c0 + c] = so[r * OPITCH + c];
    }
}

}  // namespace

extern "C" void kernel_launch(void* const* d_in, const int* in_sizes, int n_in,
                              void* d_out, int out_size) {
    const float* x = (const float*)d_in[0];
    float* o = (float*)d_out;
    dim3 grid(W / TW, H / TH);
    sobel_canny<<<grid, NT>>>(x, o);
}

// round 4
// speedup vs baseline: 1.8792x; 1.8792x over previous
#include <cuda_runtime.h>

namespace {

constexpr int H = 4096, W = 4096;
constexpr int ROWS = 32;            // output rows per block
constexpr int WPB  = 8;             // warps per block
constexpr int CPW  = 128;           // columns per warp (32 lanes x 4)

__device__ __forceinline__ float4 zero4() { return make_float4(0.f, 0.f, 0.f, 0.f); }

// A = t + 2m + b (bitwise == fadd(fadd(t, 2*m), b) since 2*m is exact)
__device__ __forceinline__ float Af(float t, float m, float b) {
    return __fadd_rn(__fmaf_rn(2.0f, m, t), b);
}
// gy = Bl + 2Bc + Br (same exactness argument)
__device__ __forceinline__ float Gy(float Bl, float Bc, float Br) {
    return __fadd_rn(__fmaf_rn(2.0f, Bc, Bl), Br);
}
__device__ __forceinline__ float Mag(float gx, float gy) {
    return __fsqrt_rn(__fadd_rn(__fmul_rn(gx, gx), __fmul_rn(gy, gy)));
}
__device__ __forceinline__ float Nms(float mc, float mp, float mn) {
    float e = ((mc >= mp) && (mc >= mn)) ? mc : 0.0f;
    return (e > 0.15f) ? 255.0f : ((e >= 0.05f) ? 0.0f : e);
}

__global__ void __launch_bounds__(WPB * 32) sobel_canny(const float* __restrict__ x,
                                                        float* __restrict__ out) {
    const int lane = threadIdx.x & 31;
    const int warp = threadIdx.x >> 5;
    const int c0 = blockIdx.x * (WPB * CPW) + warp * CPW + lane * 4;  // first of 4 cols
    const int r0 = blockIdx.y * ROWS;

    const bool isL = (lane == 0);
    const bool isR = (lane == 31);
    // halo cols: lane0 -> c0-2,c0-1 ; lane31 -> c0+4,c0+5. Either both in
    // range or both out (hc is even, >= -2, <= 4096), so one predicate.
    const int hc = isL ? (c0 - 2) : (c0 + 4);
    const bool hok = (isL || isR) && ((unsigned)hc < (unsigned)W);

    auto ldrow4 = [&](int r) -> float4 {
        if ((unsigned)r < (unsigned)H)
            return *reinterpret_cast<const float4*>(x + (size_t)r * W + c0);
        return zero4();
    };
    auto ldhalo2 = [&](int r) -> float2 {
        if (hok && (unsigned)r < (unsigned)H)
            return *reinterpret_cast<const float2*>(x + (size_t)r * W + hc);
        return make_float2(0.f, 0.f);
    };

    // rolling state: rows gr-1, gr, gr+1 (+ prefetch gr+2)
    float4 xt = ldrow4(r0 - 1), xm = ldrow4(r0), xb = ldrow4(r0 + 1);
    float2 ht = ldhalo2(r0 - 1), hm = ldhalo2(r0), hb = ldhalo2(r0 + 1);

#pragma unroll 4
    for (int gr = r0; gr < r0 + ROWS; gr++) {
        // prefetch two rows ahead
        float4 xn = ldrow4(gr + 2);
        float2 hn = ldhalo2(gr + 2);

        // column sums/diffs for this thread's 4 columns
        float A0 = Af(xt.x, xm.x, xb.x), B0 = __fsub_rn(xt.x, xb.x);
        float A1 = Af(xt.y, xm.y, xb.y), B1 = __fsub_rn(xt.y, xb.y);
        float A2 = Af(xt.z, xm.z, xb.z), B2 = __fsub_rn(xt.z, xb.z);
        float A3 = Af(xt.w, xm.w, xb.w), B3 = __fsub_rn(xt.w, xb.w);
        // halo columns (only meaningful on edge lanes)
        float hA0 = Af(ht.x, hm.x, hb.x), hB0 = __fsub_rn(ht.x, hb.x);
        float hA1 = Af(ht.y, hm.y, hb.y), hB1 = __fsub_rn(ht.y, hb.y);

        // neighbor A/B across lanes
        float Am1 = __shfl_up_sync(0xffffffffu, A3, 1);
        float Bm1 = __shfl_up_sync(0xffffffffu, B3, 1);
        float Ap4 = __shfl_down_sync(0xffffffffu, A0, 1);
        float Bp4 = __shfl_down_sync(0xffffffffu, B0, 1);
        if (isL) { Am1 = hA1; Bm1 = hB1; }
        if (isR) { Ap4 = hA0; Bp4 = hB0; }

        // gradients + magnitude at the 4 columns
        float m0 = Mag(__fsub_rn(A1, Am1), Gy(Bm1, B0, B1));
        float m1 = Mag(__fsub_rn(A2, A0),  Gy(B0,  B1, B2));
        float m2 = Mag(__fsub_rn(A3, A1),  Gy(B1,  B2, B3));
        float m3 = Mag(__fsub_rn(Ap4, A2), Gy(B2,  B3, Bp4));

        // magnitude at the warp-halo column (lane0: c0-1, lane31: c0+4)
        float gxh = isL ? __fsub_rn(A0, hA0) : __fsub_rn(hA1, A3);
        float gyh = isL ? Gy(hB0, hB1, B0)   : Gy(B3, hB0, hB1);
        float mh  = Mag(gxh, gyh);

        // neighbor magnitudes across lanes
        float mm1 = __shfl_up_sync(0xffffffffu, m3, 1);
        float mp4 = __shfl_down_sync(0xffffffffu, m0, 1);
        if (isL) mm1 = mh;
        if (isR) mp4 = mh;

        float4 o;
        o.x = Nms(m0, mm1, m1);
        o.y = Nms(m1, m0, m2);
        o.z = Nms(m2, m1, m3);
        o.w = Nms(m3, m2, mp4);

        if (gr == 0 || gr == H - 1) o = zero4();   // border rows
        if (c0 == 0) o.x = 0.0f;                   // border cols
        if (c0 + 4 == W) o.w = 0.0f;

        *reinterpret_cast<float4*>(out + (size_t)gr * W + c0) = o;

        xt = xm; xm = xb; xb = xn;
        ht = hm; hm = hb; hb = hn;
    }
}

}  // namespace

extern "C" void kernel_launch(void* const* d_in, const int* in_sizes, int n_in,
                              void* d_out, int out_size) {
    const float* x = (const float*)d_in[0];
    float* o = (float*)d_out;
    dim3 grid(W / (WPB * CPW), H / ROWS);
    sobel_canny<<<grid, WPB * 32>>>(x, o);
}

// round 8
// speedup vs baseline: 1.9882x; 1.0580x over previous
#include <cuda_runtime.h>

namespace {

constexpr int H = 4096, W = 4096;
constexpr int ROWS = 16;            // output rows per block
constexpr int WPB  = 8;             // warps per block
constexpr int CPW  = 128;           // columns per warp (32 lanes x 4)

__device__ __forceinline__ float4 zero4() { return make_float4(0.f, 0.f, 0.f, 0.f); }

// A = t + 2m + b ; gy = Bl + 2Bc + Br  (2*m exact, so fmaf is bitwise == the reference chain)
__device__ __forceinline__ float Af(float t, float m, float b) {
    return __fadd_rn(__fmaf_rn(2.0f, m, t), b);
}
__device__ __forceinline__ float Gy(float Bl, float Bc, float Br) {
    return __fadd_rn(__fmaf_rn(2.0f, Bc, Bl), Br);
}
__device__ __forceinline__ float Mag(float gx, float gy) {
    return __fsqrt_rn(__fadd_rn(__fmul_rn(gx, gx), __fmul_rn(gy, gy)));
}
// (mc>=mp && mc>=mn) == mc >= max(mp,mn) for non-NaN inputs
__device__ __forceinline__ float Nms(float mc, float mp, float mn) {
    float e = (mc >= fmaxf(mp, mn)) ? mc : 0.0f;
    return (e > 0.15f) ? 255.0f : ((e >= 0.05f) ? 0.0f : e);
}

template <bool GUARD>
__device__ __forceinline__ void tile(const float* __restrict__ x, float* __restrict__ out) {
    const int lane = threadIdx.x & 31;
    const int warp = threadIdx.x >> 5;
    const int c0 = blockIdx.x * (WPB * CPW) + warp * CPW + lane * 4;
    const int r0 = blockIdx.y * ROWS;

    const bool isL = (lane == 0);
    const bool isR = (lane == 31);
    const int hc = isL ? (c0 - 2) : (c0 + 4);
    const bool hok = (isL || isR) && ((unsigned)hc < (unsigned)W);

    const float* p  = x + (size_t)r0 * W + c0;   // row gr (current output row)
    const float* ph = x + (size_t)r0 * W + hc;   // halo cols, same row
    float*       q  = out + (size_t)r0 * W + c0;

    auto ld4 = [&](const float* a, int r) -> float4 {
        if (!GUARD || (unsigned)r < (unsigned)H)
            return *reinterpret_cast<const float4*>(a);
        return zero4();
    };
    auto ld2 = [&](const float* a, int r) -> float2 {
        if (hok && (!GUARD || (unsigned)r < (unsigned)H))
            return *reinterpret_cast<const float2*>(a);
        return make_float2(0.f, 0.f);
    };

    float4 xt = ld4(p - W, r0 - 1), xm = ld4(p, r0), xb = ld4(p + W, r0 + 1);
    float2 ht = ld2(ph - W, r0 - 1), hm = ld2(ph, r0), hb = ld2(ph + W, r0 + 1);

#pragma unroll 4
    for (int i = 0; i < ROWS; i++) {
        const int gr = r0 + i;
        // prefetch row gr+2 (immediate-offset loads, pointers advance below)
        float4 xn = ld4(p + 2 * W, gr + 2);
        float2 hn = ld2(ph + 2 * W, gr + 2);

        float A0 = Af(xt.x, xm.x, xb.x), B0 = __fsub_rn(xt.x, xb.x);
        float A1 = Af(xt.y, xm.y, xb.y), B1 = __fsub_rn(xt.y, xb.y);
        float A2 = Af(xt.z, xm.z, xb.z), B2 = __fsub_rn(xt.z, xb.z);
        float A3 = Af(xt.w, xm.w, xb.w), B3 = __fsub_rn(xt.w, xb.w);
        float hA0 = Af(ht.x, hm.x, hb.x), hB0 = __fsub_rn(ht.x, hb.x);
        float hA1 = Af(ht.y, hm.y, hb.y), hB1 = __fsub_rn(ht.y, hb.y);

        float Am1 = __shfl_up_sync(0xffffffffu, A3, 1);
        float Bm1 = __shfl_up_sync(0xffffffffu, B3, 1);
        float Ap4 = __shfl_down_sync(0xffffffffu, A0, 1);
        float Bp4 = __shfl_down_sync(0xffffffffu, B0, 1);
        if (isL) { Am1 = hA1; Bm1 = hB1; }
        if (isR) { Ap4 = hA0; Bp4 = hB0; }

        float m0 = Mag(__fsub_rn(A1, Am1), Gy(Bm1, B0, B1));
        float m1 = Mag(__fsub_rn(A2, A0),  Gy(B0,  B1, B2));
        float m2 = Mag(__fsub_rn(A3, A1),  Gy(B1,  B2, B3));
        float m3 = Mag(__fsub_rn(Ap4, A2), Gy(B2,  B3, Bp4));

        float gxh = isL ? __fsub_rn(A0, hA0) : __fsub_rn(hA1, A3);
        float gyh = isL ? Gy(hB0, hB1, B0)   : Gy(B3, hB0, hB1);
        float mh  = Mag(gxh, gyh);

        float mm1 = __shfl_up_sync(0xffffffffu, m3, 1);
        float mp4 = __shfl_down_sync(0xffffffffu, m0, 1);
        if (isL) mm1 = mh;
        if (isR) mp4 = mh;

        float4 o;
        o.x = Nms(m0, mm1, m1);
        o.y = Nms(m1, m0, m2);
        o.z = Nms(m2, m1, m3);
        o.w = Nms(m3, m2, mp4);

        if (GUARD && (gr == 0 || gr == H - 1)) o = zero4();
        if (c0 == 0) o.x = 0.0f;
        if (c0 + 4 == W) o.w = 0.0f;

        *reinterpret_cast<float4*>(q) = o;

        p += W; ph += W; q += W;
        xt = xm; xm = xb; xb = xn;
        ht = hm; hm = hb; hb = hn;
    }
}

__global__ void __launch_bounds__(WPB * 32) sobel_canny(const float* __restrict__ x,
                                                        float* __restrict__ out) {
    if (blockIdx.y == 0 || blockIdx.y == gridDim.y - 1)
        tile<true>(x, out);
    else
        tile<false>(x, out);
}

}  // namespace

extern "C" void kernel_launch(void* const* d_in, const int* in_sizes, int n_in,
                              void* d_out, int out_size) {
    const float* x = (const float*)d_in[0];
    float* o = (float*)d_out;
    dim3 grid(W / (WPB * CPW), H / ROWS);
    sobel_canny<<<grid, WPB * 32>>>(x, o);
}

// round 10
// speedup vs baseline: 2.1353x; 1.0740x over previous
#include <cuda_runtime.h>

namespace {

constexpr int H = 4096, W = 4096;
constexpr int ROWS = 16;            // output rows per block
constexpr int WPB  = 4;             // warps per block
constexpr int CPW  = 256;           // cols per warp (32 lanes x 8)
constexpr int CPB  = WPB * CPW;     // 1024 cols per block
constexpr int NT   = WPB * 32;

__device__ __forceinline__ float Af(float t, float m, float b) {
    return __fadd_rn(__fmaf_rn(2.0f, m, t), b);     // t + 2m + b (2m exact)
}
__device__ __forceinline__ float GyF(float l, float c, float r) {
    return __fadd_rn(__fmaf_rn(2.0f, c, l), r);     // l + 2c + r
}
__device__ __forceinline__ float Sq(float gx, float gy) {
    return __fadd_rn(__fmul_rn(gx, gx), __fmul_rn(gy, gy));
}

// Exact reference chain on squared magnitudes (rare path).
__device__ __forceinline__ float slowNms(float sp, float sc, float sn) {
    float mp = __fsqrt_rn(sp), mc = __fsqrt_rn(sc), mn = __fsqrt_rn(sn);
    float e = ((mc >= mp) && (mc >= mn)) ? mc : 0.0f;
    return (e > 0.15f) ? 255.0f : ((e >= 0.05f) ? 0.0f : e);
}

// Squared-domain fast decision. Sets `slow` when the squared-domain result is
// not provably identical to the sqrt-domain reference (rounding-tie bands) or
// when the actual sqrt value is needed (kept & below-low pass-through).
__device__ __forceinline__ float fastNms(float sp, float sc, float sn, bool& slow) {
    float mx = fmaxf(sp, sn);
    bool kept   = (sc >= mx);                              // exact keep (monotone sqrt)
    bool defDrop = (mx >= __fmul_rn(sc, 1.000001f));       // exact drop (margin >> 2^-22)
    slow = !defDrop && (!kept
                        || (sc < 0.0025001f)               // needs sqrt value / low boundary
                        || (sc > 0.0224999f && sc < 0.0225001f));  // high boundary band
    return (kept && sc > 0.0225001f) ? 255.0f : 0.0f;
}

template <bool GUARD>
__device__ __forceinline__ void tile(const float* __restrict__ x, float* __restrict__ out) {
    const int lane = threadIdx.x & 31;
    const int warp = threadIdx.x >> 5;
    const int c0 = blockIdx.x * CPB + warp * CPW + lane * 8;
    const int r0 = blockIdx.y * ROWS;

    const bool isL = (lane == 0);
    const bool isR = (lane == 31);
    const int hc = isL ? (c0 - 2) : (c0 + 8);
    const bool hok = (isL || isR) && ((unsigned)hc < (unsigned)W);

    const float* p  = x + (size_t)r0 * W + c0;
    const float* ph = x + (size_t)r0 * W + hc;
    float*       q  = out + (size_t)r0 * W + c0;

    auto ld8 = [&](const float* a, int r, float4& u, float4& v) {
        if (!GUARD || (unsigned)r < (unsigned)H) {
            u = *reinterpret_cast<const float4*>(a);
            v = *reinterpret_cast<const float4*>(a + 4);
        } else {
            u = make_float4(0.f, 0.f, 0.f, 0.f);
            v = make_float4(0.f, 0.f, 0.f, 0.f);
        }
    };
    auto ld2 = [&](const float* a, int r) -> float2 {
        if (hok && (!GUARD || (unsigned)r < (unsigned)H))
            return *reinterpret_cast<const float2*>(a);
        return make_float2(0.f, 0.f);
    };

    float4 tA, tB, mA, mB, bA, bB;
    ld8(p - W, r0 - 1, tA, tB);
    ld8(p,     r0,     mA, mB);
    ld8(p + W, r0 + 1, bA, bB);
    float2 ht = ld2(ph - W, r0 - 1), hm = ld2(ph, r0), hb = ld2(ph + W, r0 + 1);

#pragma unroll 4
    for (int i = 0; i < ROWS; i++) {
        const int gr = r0 + i;
        float4 nA, nB;
        ld8(p + 2 * W, gr + 2, nA, nB);          // prefetch row gr+2
        float2 hn = ld2(ph + 2 * W, gr + 2);

        // column sums/diffs
        float A0 = Af(tA.x, mA.x, bA.x), B0 = __fsub_rn(tA.x, bA.x);
        float A1 = Af(tA.y, mA.y, bA.y), B1 = __fsub_rn(tA.y, bA.y);
        float A2 = Af(tA.z, mA.z, bA.z), B2 = __fsub_rn(tA.z, bA.z);
        float A3 = Af(tA.w, mA.w, bA.w), B3 = __fsub_rn(tA.w, bA.w);
        float A4 = Af(tB.x, mB.x, bB.x), B4 = __fsub_rn(tB.x, bB.x);
        float A5 = Af(tB.y, mB.y, bB.y), B5 = __fsub_rn(tB.y, bB.y);
        float A6 = Af(tB.z, mB.z, bB.z), B6 = __fsub_rn(tB.z, bB.z);
        float A7 = Af(tB.w, mB.w, bB.w), B7 = __fsub_rn(tB.w, bB.w);
        float hA0 = Af(ht.x, hm.x, hb.x), hB0 = __fsub_rn(ht.x, hb.x);
        float hA1 = Af(ht.y, hm.y, hb.y), hB1 = __fsub_rn(ht.y, hb.y);

        // cross-lane A/B neighbors
        float Am1 = __shfl_up_sync(0xffffffffu, A7, 1);
        float Bm1 = __shfl_up_sync(0xffffffffu, B7, 1);
        float Ap8 = __shfl_down_sync(0xffffffffu, A0, 1);
        float Bp8 = __shfl_down_sync(0xffffffffu, B0, 1);
        if (isL) { Am1 = hA1; Bm1 = hB1; }
        if (isR) { Ap8 = hA0; Bp8 = hB0; }

        // squared magnitudes at the 8 columns
        float s0 = Sq(__fsub_rn(A1, Am1), GyF(Bm1, B0, B1));
        float s1 = Sq(__fsub_rn(A2, A0),  GyF(B0, B1, B2));
        float s2 = Sq(__fsub_rn(A3, A1),  GyF(B1, B2, B3));
        float s3 = Sq(__fsub_rn(A4, A2),  GyF(B2, B3, B4));
        float s4 = Sq(__fsub_rn(A5, A3),  GyF(B3, B4, B5));
        float s5 = Sq(__fsub_rn(A6, A4),  GyF(B4, B5, B6));
        float s6 = Sq(__fsub_rn(A7, A5),  GyF(B5, B6, B7));
        float s7 = Sq(__fsub_rn(Ap8, A6), GyF(B6, B7, Bp8));

        // squared magnitude at warp-halo column (lane0: c0-1, lane31: c0+8)
        float gxh = isL ? __fsub_rn(A0, hA0) : __fsub_rn(hA1, A7);
        float gyh = isL ? GyF(hB0, hB1, B0)  : GyF(B7, hB0, hB1);
        float sh  = Sq(gxh, gyh);

        // cross-lane s neighbors
        float sm1 = __shfl_up_sync(0xffffffffu, s7, 1);
        float sp8 = __shfl_down_sync(0xffffffffu, s0, 1);
        if (isL) sm1 = sh;
        if (isR) sp8 = sh;

        bool w0, w1, w2, w3, w4, w5, w6, w7;
        float o0 = fastNms(sm1, s0, s1, w0);
        float o1 = fastNms(s0,  s1, s2, w1);
        float o2 = fastNms(s1,  s2, s3, w2);
        float o3 = fastNms(s2,  s3, s4, w3);
        float o4 = fastNms(s3,  s4, s5, w4);
        float o5 = fastNms(s4,  s5, s6, w5);
        float o6 = fastNms(s5,  s6, s7, w6);
        float o7 = fastNms(s6,  s7, sp8, w7);

        bool anySlow = w0 | w1 | w2 | w3 | w4 | w5 | w6 | w7;
        if (__any_sync(0xffffffffu, anySlow)) {
            if (w0) o0 = slowNms(sm1, s0, s1);
            if (w1) o1 = slowNms(s0,  s1, s2);
            if (w2) o2 = slowNms(s1,  s2, s3);
            if (w3) o3 = slowNms(s2,  s3, s4);
            if (w4) o4 = slowNms(s3,  s4, s5);
            if (w5) o5 = slowNms(s4,  s5, s6);
            if (w6) o6 = slowNms(s5,  s6, s7);
            if (w7) o7 = slowNms(s6,  s7, sp8);
        }

        if (GUARD && (gr == 0 || gr == H - 1)) {
            o0 = o1 = o2 = o3 = o4 = o5 = o6 = o7 = 0.0f;
        }
        if (c0 == 0) o0 = 0.0f;          // image left border
        if (c0 + 8 == W) o7 = 0.0f;      // image right border

        *reinterpret_cast<float4*>(q)     = make_float4(o0, o1, o2, o3);
        *reinterpret_cast<float4*>(q + 4) = make_float4(o4, o5, o6, o7);

        p += W; ph += W; q += W;
        tA = mA; tB = mB; mA = bA; mB = bB; bA = nA; bB = nB;
        ht = hm; hm = hb; hb = hn;
    }
}

__global__ void __launch_bounds__(NT) sobel_canny(const float* __restrict__ x,
                                                  float* __restrict__ out) {
    if (blockIdx.y == 0 || blockIdx.y == gridDim.y - 1)
        tile<true>(x, out);
    else
        tile<false>(x, out);
}

}  // namespace

extern "C" void kernel_launch(void* const* d_in, const int* in_sizes, int n_in,
                              void* d_out, int out_size) {
    const float* x = (const float*)d_in[0];
    float* o = (float*)d_out;
    dim3 grid(W / CPB, H / ROWS);
    sobel_canny<<<grid, NT>>>(x, o);
}

// round 11
// speedup vs baseline: 2.4232x; 1.1348x over previous
#include <cuda_runtime.h>

namespace {

constexpr int H = 4096, W = 4096;
constexpr int ROWS = 16;            // output rows per block
constexpr int WPB  = 4;             // warps per block
constexpr int CPW  = 256;           // cols per warp (32 lanes x 8)
constexpr int CPB  = WPB * CPW;     // 1024 cols per block
constexpr int NT   = WPB * 32;

__device__ __forceinline__ float Af(float t, float m, float b) {
    return __fadd_rn(__fmaf_rn(2.0f, m, t), b);     // t + 2m + b (2m exact)
}
__device__ __forceinline__ float GyF(float l, float c, float r) {
    return __fadd_rn(__fmaf_rn(2.0f, c, l), r);     // l + 2c + r
}
__device__ __forceinline__ float Sq(float gx, float gy) {
    return __fadd_rn(__fmul_rn(gx, gx), __fmul_rn(gy, gy));
}

// Exact reference chain on squared magnitudes (rare path).
__device__ __forceinline__ float slowNms(float sp, float sc, float sn) {
    float mp = __fsqrt_rn(sp), mc = __fsqrt_rn(sc), mn = __fsqrt_rn(sn);
    float e = ((mc >= mp) && (mc >= mn)) ? mc : 0.0f;
    return (e > 0.15f) ? 255.0f : ((e >= 0.05f) ? 0.0f : e);
}

// Squared-domain fast decision.
//  - !keptL  : mc strictly below neighbor max after sqrt (8-ulp margin) -> 0, exact.
//  - kept && strong : local max with sqrt(sc) > 0.15 by wide margin -> 255, exact.
//  - everything else -> slow (near-ties, kept weak/low/threshold bands).
__device__ __forceinline__ float fastNms(float sp, float sc, float sn, bool& slow) {
    float mx = fmaxf(sp, sn);
    bool kept   = (sc >= mx);
    bool keptL  = (__fmul_rn(sc, 1.000001f) >= mx);
    bool strong = (sc > 0.0225001f);
    bool hit = kept && strong;
    slow = keptL && !hit;
    return hit ? 255.0f : 0.0f;
}

template <bool GUARD>
__device__ __forceinline__ void tile(const float* __restrict__ x, float* __restrict__ out) {
    const int lane = threadIdx.x & 31;
    const int warp = threadIdx.x >> 5;
    const int c0 = blockIdx.x * CPB + warp * CPW + lane * 8;
    const int r0 = blockIdx.y * ROWS;

    const bool isL = (lane == 0);
    const bool isR = (lane == 31);
    const int hc = isL ? (c0 - 2) : (c0 + 8);
    const bool hok = (isL || isR) && ((unsigned)hc < (unsigned)W);

    const float* p  = x + (size_t)r0 * W + c0;
    const float* ph = x + (size_t)r0 * W + hc;
    float*       q  = out + (size_t)r0 * W + c0;

    auto ld8 = [&](const float* a, int r, float4& u, float4& v) {
        if (!GUARD || (unsigned)r < (unsigned)H) {
            u = *reinterpret_cast<const float4*>(a);
            v = *reinterpret_cast<const float4*>(a + 4);
        } else {
            u = make_float4(0.f, 0.f, 0.f, 0.f);
            v = make_float4(0.f, 0.f, 0.f, 0.f);
        }
    };
    auto ld2 = [&](const float* a, int r) -> float2 {
        if (hok && (!GUARD || (unsigned)r < (unsigned)H))
            return *reinterpret_cast<const float2*>(a);
        return make_float2(0.f, 0.f);
    };

    float4 tA, tB, mA, mB, bA, bB;
    ld8(p - W, r0 - 1, tA, tB);
    ld8(p,     r0,     mA, mB);
    ld8(p + W, r0 + 1, bA, bB);
    float2 ht = ld2(ph - W, r0 - 1), hm = ld2(ph, r0), hb = ld2(ph + W, r0 + 1);

#pragma unroll 4
    for (int i = 0; i < ROWS; i++) {
        const int gr = r0 + i;
        float4 nA, nB;
        ld8(p + 2 * W, gr + 2, nA, nB);          // prefetch row gr+2
        float2 hn = ld2(ph + 2 * W, gr + 2);

        // column sums/diffs
        float A0 = Af(tA.x, mA.x, bA.x), B0 = __fsub_rn(tA.x, bA.x);
        float A1 = Af(tA.y, mA.y, bA.y), B1 = __fsub_rn(tA.y, bA.y);
        float A2 = Af(tA.z, mA.z, bA.z), B2 = __fsub_rn(tA.z, bA.z);
        float A3 = Af(tA.w, mA.w, bA.w), B3 = __fsub_rn(tA.w, bA.w);
        float A4 = Af(tB.x, mB.x, bB.x), B4 = __fsub_rn(tB.x, bB.x);
        float A5 = Af(tB.y, mB.y, bB.y), B5 = __fsub_rn(tB.y, bB.y);
        float A6 = Af(tB.z, mB.z, bB.z), B6 = __fsub_rn(tB.z, bB.z);
        float A7 = Af(tB.w, mB.w, bB.w), B7 = __fsub_rn(tB.w, bB.w);
        float hA0 = Af(ht.x, hm.x, hb.x), hB0 = __fsub_rn(ht.x, hb.x);
        float hA1 = Af(ht.y, hm.y, hb.y), hB1 = __fsub_rn(ht.y, hb.y);

        // single round of 8 independent shuffles: +/-1 and +/-2 column context
        float Am1 = __shfl_up_sync(0xffffffffu, A7, 1);
        float Bm1 = __shfl_up_sync(0xffffffffu, B7, 1);
        float Am2 = __shfl_up_sync(0xffffffffu, A6, 1);
        float Bm2 = __shfl_up_sync(0xffffffffu, B6, 1);
        float Ap8 = __shfl_down_sync(0xffffffffu, A0, 1);
        float Bp8 = __shfl_down_sync(0xffffffffu, B0, 1);
        float Ap9 = __shfl_down_sync(0xffffffffu, A1, 1);
        float Bp9 = __shfl_down_sync(0xffffffffu, B1, 1);
        if (isL) { Am1 = hA1; Bm1 = hB1; Am2 = hA0; Bm2 = hB0; }
        if (isR) { Ap8 = hA0; Bp8 = hB0; Ap9 = hA1; Bp9 = hB1; }

        // squared magnitudes (sm1/sp8 bitwise == neighbor lane's s7/s0)
        float sm1 = Sq(__fsub_rn(A0, Am2),  GyF(Bm2, Bm1, B0));
        float s0  = Sq(__fsub_rn(A1, Am1),  GyF(Bm1, B0, B1));
        float s1  = Sq(__fsub_rn(A2, A0),   GyF(B0, B1, B2));
        float s2  = Sq(__fsub_rn(A3, A1),   GyF(B1, B2, B3));
        float s3  = Sq(__fsub_rn(A4, A2),   GyF(B2, B3, B4));
        float s4  = Sq(__fsub_rn(A5, A3),   GyF(B3, B4, B5));
        float s5  = Sq(__fsub_rn(A6, A4),   GyF(B4, B5, B6));
        float s6  = Sq(__fsub_rn(A7, A5),   GyF(B5, B6, B7));
        float s7  = Sq(__fsub_rn(Ap8, A6),  GyF(B6, B7, Bp8));
        float sp8 = Sq(__fsub_rn(Ap9, A7),  GyF(B7, Bp8, Bp9));

        bool w0, w1, w2, w3, w4, w5, w6, w7;
        float o0 = fastNms(sm1, s0, s1, w0);
        float o1 = fastNms(s0,  s1, s2, w1);
        float o2 = fastNms(s1,  s2, s3, w2);
        float o3 = fastNms(s2,  s3, s4, w3);
        float o4 = fastNms(s3,  s4, s5, w4);
        float o5 = fastNms(s4,  s5, s6, w5);
        float o6 = fastNms(s5,  s6, s7, w6);
        float o7 = fastNms(s6,  s7, sp8, w7);

        bool anySlow = w0 | w1 | w2 | w3 | w4 | w5 | w6 | w7;
        if (__any_sync(0xffffffffu, anySlow)) {
            if (w0) o0 = slowNms(sm1, s0, s1);
            if (w1) o1 = slowNms(s0,  s1, s2);
            if (w2) o2 = slowNms(s1,  s2, s3);
            if (w3) o3 = slowNms(s2,  s3, s4);
            if (w4) o4 = slowNms(s3,  s4, s5);
            if (w5) o5 = slowNms(s4,  s5, s6);
            if (w6) o6 = slowNms(s5,  s6, s7);
            if (w7) o7 = slowNms(s6,  s7, sp8);
        }

        if (GUARD && (gr == 0 || gr == H - 1)) {
            o0 = o1 = o2 = o3 = o4 = o5 = o6 = o7 = 0.0f;
        }
        if (c0 == 0) o0 = 0.0f;          // image left border
        if (c0 + 8 == W) o7 = 0.0f;      // image right border

        *reinterpret_cast<float4*>(q)     = make_float4(o0, o1, o2, o3);
        *reinterpret_cast<float4*>(q + 4) = make_float4(o4, o5, o6, o7);

        p += W; ph += W; q += W;
        tA = mA; tB = mB; mA = bA; mB = bB; bA = nA; bB = nB;
        ht = hm; hm = hb; hb = hn;
    }
}

__global__ void __launch_bounds__(NT) sobel_canny(const float* __restrict__ x,
                                                  float* __restrict__ out) {
    if (blockIdx.y == 0 || blockIdx.y == gridDim.y - 1)
        tile<true>(x, out);
    else
        tile<false>(x, out);
}

}  // namespace

extern "C" void kernel_launch(void* const* d_in, const int* in_sizes, int n_in,
                              void* d_out, int out_size) {
    const float* x = (const float*)d_in[0];
    float* o = (float*)d_out;
    dim3 grid(W / CPB, H / ROWS);
    sobel_canny<<<grid, NT>>>(x, o);
}

// round 12
// speedup vs baseline: 2.6550x; 1.0956x over previous
#include <cuda_runtime.h>

namespace {

constexpr int H = 4096, W = 4096;
constexpr int ROWS = 8;             // output rows per block
constexpr int WPB  = 4;             // warps per block
constexpr int CPW  = 256;           // cols per warp (32 lanes x 8)
constexpr int CPB  = WPB * CPW;     // 1024 cols per block
constexpr int NT   = WPB * 32;

__device__ __forceinline__ float Af(float t, float m, float b) {
    return __fadd_rn(__fmaf_rn(2.0f, m, t), b);     // t + 2m + b (2m exact)
}
__device__ __forceinline__ float GyF(float l, float c, float r) {
    return __fadd_rn(__fmaf_rn(2.0f, c, l), r);     // l + 2c + r
}
__device__ __forceinline__ float Sq(float gx, float gy) {
    return __fadd_rn(__fmul_rn(gx, gx), __fmul_rn(gy, gy));
}

// Exact reference chain on squared magnitudes (rare path).
__device__ __forceinline__ float slowNms(float sp, float sc, float sn) {
    float mp = __fsqrt_rn(sp), mc = __fsqrt_rn(sc), mn = __fsqrt_rn(sn);
    float e = ((mc >= mp) && (mc >= mn)) ? mc : 0.0f;
    return (e > 0.15f) ? 255.0f : ((e >= 0.05f) ? 0.0f : e);
}

// Squared-domain fast decision.
//  - !keptL  : mc strictly below neighbor max after sqrt (8-ulp margin) -> 0, exact.
//  - kept && strong : local max with sqrt(sc) > 0.15 by wide margin -> 255, exact.
//  - everything else -> slow (near-ties, kept weak/low/threshold bands).
__device__ __forceinline__ float fastNms(float sp, float sc, float sn, bool& slow) {
    float mx = fmaxf(sp, sn);
    bool kept   = (sc >= mx);
    bool keptL  = (__fmul_rn(sc, 1.000001f) >= mx);
    bool strong = (sc > 0.0225001f);
    bool hit = kept && strong;
    slow = keptL && !hit;
    return hit ? 255.0f : 0.0f;
}

template <bool GUARD>
__device__ __forceinline__ void tile(const float* __restrict__ x, float* __restrict__ out) {
    const int lane = threadIdx.x & 31;
    const int warp = threadIdx.x >> 5;
    const int c0 = blockIdx.x * CPB + warp * CPW + lane * 8;
    const int r0 = blockIdx.y * ROWS;

    const bool isL = (lane == 0);
    const bool isR = (lane == 31);
    const int hc = isL ? (c0 - 2) : (c0 + 8);
    const bool hok = (isL || isR) && ((unsigned)hc < (unsigned)W);

    const float* p  = x + (size_t)r0 * W + c0;
    const float* ph = x + (size_t)r0 * W + hc;
    float*       q  = out + (size_t)r0 * W + c0;

    auto ld8 = [&](const float* a, int r, float4& u, float4& v) {
        if (!GUARD || (unsigned)r < (unsigned)H) {
            u = *reinterpret_cast<const float4*>(a);
            v = *reinterpret_cast<const float4*>(a + 4);
        } else {
            u = make_float4(0.f, 0.f, 0.f, 0.f);
            v = make_float4(0.f, 0.f, 0.f, 0.f);
        }
    };
    auto ld2 = [&](const float* a, int r) -> float2 {
        if (hok && (!GUARD || (unsigned)r < (unsigned)H))
            return *reinterpret_cast<const float2*>(a);
        return make_float2(0.f, 0.f);
    };

    float4 tA, tB, mA, mB, bA, bB;
    ld8(p - W, r0 - 1, tA, tB);
    ld8(p,     r0,     mA, mB);
    ld8(p + W, r0 + 1, bA, bB);
    float2 ht = ld2(ph - W, r0 - 1), hm = ld2(ph, r0), hb = ld2(ph + W, r0 + 1);

#pragma unroll 4
    for (int i = 0; i < ROWS; i++) {
        const int gr = r0 + i;
        float4 nA, nB;
        ld8(p + 2 * W, gr + 2, nA, nB);          // prefetch row gr+2
        float2 hn = ld2(ph + 2 * W, gr + 2);

        // column sums/diffs
        float A0 = Af(tA.x, mA.x, bA.x), B0 = __fsub_rn(tA.x, bA.x);
        float A1 = Af(tA.y, mA.y, bA.y), B1 = __fsub_rn(tA.y, bA.y);
        float A2 = Af(tA.z, mA.z, bA.z), B2 = __fsub_rn(tA.z, bA.z);
        float A3 = Af(tA.w, mA.w, bA.w), B3 = __fsub_rn(tA.w, bA.w);
        float A4 = Af(tB.x, mB.x, bB.x), B4 = __fsub_rn(tB.x, bB.x);
        float A5 = Af(tB.y, mB.y, bB.y), B5 = __fsub_rn(tB.y, bB.y);
        float A6 = Af(tB.z, mB.z, bB.z), B6 = __fsub_rn(tB.z, bB.z);
        float A7 = Af(tB.w, mB.w, bB.w), B7 = __fsub_rn(tB.w, bB.w);
        float hA0 = Af(ht.x, hm.x, hb.x), hB0 = __fsub_rn(ht.x, hb.x);
        float hA1 = Af(ht.y, hm.y, hb.y), hB1 = __fsub_rn(ht.y, hb.y);

        // single round of 8 independent shuffles: +/-1 and +/-2 column context
        float Am1 = __shfl_up_sync(0xffffffffu, A7, 1);
        float Bm1 = __shfl_up_sync(0xffffffffu, B7, 1);
        float Am2 = __shfl_up_sync(0xffffffffu, A6, 1);
        float Bm2 = __shfl_up_sync(0xffffffffu, B6, 1);
        float Ap8 = __shfl_down_sync(0xffffffffu, A0, 1);
        float Bp8 = __shfl_down_sync(0xffffffffu, B0, 1);
        float Ap9 = __shfl_down_sync(0xffffffffu, A1, 1);
        float Bp9 = __shfl_down_sync(0xffffffffu, B1, 1);
        if (isL) { Am1 = hA1; Bm1 = hB1; Am2 = hA0; Bm2 = hB0; }
        if (isR) { Ap8 = hA0; Bp8 = hB0; Ap9 = hA1; Bp9 = hB1; }

        // squared magnitudes (sm1/sp8 bitwise == neighbor lane's s7/s0)
        float sm1 = Sq(__fsub_rn(A0, Am2),  GyF(Bm2, Bm1, B0));
        float s0  = Sq(__fsub_rn(A1, Am1),  GyF(Bm1, B0, B1));
        float s1  = Sq(__fsub_rn(A2, A0),   GyF(B0, B1, B2));
        float s2  = Sq(__fsub_rn(A3, A1),   GyF(B1, B2, B3));
        float s3  = Sq(__fsub_rn(A4, A2),   GyF(B2, B3, B4));
        float s4  = Sq(__fsub_rn(A5, A3),   GyF(B3, B4, B5));
        float s5  = Sq(__fsub_rn(A6, A4),   GyF(B4, B5, B6));
        float s6  = Sq(__fsub_rn(A7, A5),   GyF(B5, B6, B7));
        float s7  = Sq(__fsub_rn(Ap8, A6),  GyF(B6, B7, Bp8));
        float sp8 = Sq(__fsub_rn(Ap9, A7),  GyF(B7, Bp8, Bp9));

        bool w0, w1, w2, w3, w4, w5, w6, w7;
        float o0 = fastNms(sm1, s0, s1, w0);
        float o1 = fastNms(s0,  s1, s2, w1);
        float o2 = fastNms(s1,  s2, s3, w2);
        float o3 = fastNms(s2,  s3, s4, w3);
        float o4 = fastNms(s3,  s4, s5, w4);
        float o5 = fastNms(s4,  s5, s6, w5);
        float o6 = fastNms(s5,  s6, s7, w6);
        float o7 = fastNms(s6,  s7, sp8, w7);

        bool anySlow = w0 | w1 | w2 | w3 | w4 | w5 | w6 | w7;
        if (__any_sync(0xffffffffu, anySlow)) {
            if (w0) o0 = slowNms(sm1, s0, s1);
            if (w1) o1 = slowNms(s0,  s1, s2);
            if (w2) o2 = slowNms(s1,  s2, s3);
            if (w3) o3 = slowNms(s2,  s3, s4);
            if (w4) o4 = slowNms(s3,  s4, s5);
            if (w5) o5 = slowNms(s4,  s5, s6);
            if (w6) o6 = slowNms(s5,  s6, s7);
            if (w7) o7 = slowNms(s6,  s7, sp8);
        }

        if (GUARD && (gr == 0 || gr == H - 1)) {
            o0 = o1 = o2 = o3 = o4 = o5 = o6 = o7 = 0.0f;
        }
        if (c0 == 0) o0 = 0.0f;          // image left border
        if (c0 + 8 == W) o7 = 0.0f;      // image right border

        // streaming stores: output is never re-read; keep L2 for input halo rows
        __stcs(reinterpret_cast<float4*>(q),     make_float4(o0, o1, o2, o3));
        __stcs(reinterpret_cast<float4*>(q + 4), make_float4(o4, o5, o6, o7));

        p += W; ph += W; q += W;
        tA = mA; tB = mB; mA = bA; mB = bB; bA = nA; bB = nB;
        ht = hm; hm = hb; hb = hn;
    }
}

__global__ void __launch_bounds__(NT, 8) sobel_canny(const float* __restrict__ x,
                                                     float* __restrict__ out) {
    if (blockIdx.y == 0 || blockIdx.y == gridDim.y - 1)
        tile<true>(x, out);
    else
        tile<false>(x, out);
}

}  // namespace

extern "C" void kernel_launch(void* const* d_in, const int* in_sizes, int n_in,
                              void* d_out, int out_size) {
    const float* x = (const float*)d_in[0];
    float* o = (float*)d_out;
    dim3 grid(W / CPB, H / ROWS);
    sobel_canny<<<grid, NT>>>(x, o);
}